// round 1
// baseline (speedup 1.0000x reference)
#include <cuda_runtime.h>
#include <math.h>

// ---------------------------------------------------------------------------
// WarpNet: two 3x3 conv+BN+ReLU (512->128, 512->256), shifted-window softmax
// distance weights (d=2, k=5), weighted warp + average, 1x1 conv head (124
// classes) + log_softmax.
//
// Shapes (fixed by the problem):
//   clip_embs : (4, 512, 64, 64) fp32
//   emb_W     : (256, 512, 3, 3)    emb2_W : (128, 512, 3, 3)
//   last_W    : (124, 256, 1, 1)    last_b : (124,)
// Output tuple: x (2,124,64,64) then clip_emb2 (4,128,64,64), concatenated.
// ---------------------------------------------------------------------------

#define NIMG   4
#define CIN    512
#define HW     64
#define C1     256   // emb channels
#define C2     128   // emb2 channels
#define NCLS   124
#define NPAIR  2

#define X_ELEMS (2 * NCLS * HW * HW)        // 1,015,808

// Scratch (device globals — no allocations allowed)
__device__ float g_sbuf [NIMG * C1 * HW * HW];        // clip_emb_s (NCHW)
__device__ float g_y2   [NPAIR * HW * HW];            // sum_c other^2
__device__ float g_wgt  [25 * NPAIR * HW * HW];       // softmax weights (o,n,h,w)
__device__ float g_final[NPAIR * HW * HW * C1];       // final_fea, NHWC
__device__ float g_WT   [256 * NCLS];                 // last_W transposed (c, o)

// ---------------------------------------------------------------------------
// Conv 3x3 SAME + BN + ReLU.  Block tile: 64 out-channels x (8h x 32w) pixels,
// 256 threads, each thread computes 8co x 8px.  K loop in chunks of 8 input
// channels staged in smem.
// ---------------------------------------------------------------------------
template<int COUT, bool TO_SBUF>
__global__ __launch_bounds__(256, 2)
void conv3x3_bn_relu(const float* __restrict__ in,  const float* __restrict__ wt,
                     const float* __restrict__ bg,  const float* __restrict__ bb,
                     const float* __restrict__ bm,  const float* __restrict__ bv,
                     float* __restrict__ out_ext)
{
    __shared__ float s_in[8][10][36];   // [ci][h0-1..h0+8][w0-1..w0+32] (+pad)
    __shared__ float s_w [64][72];      // [co_rel][ci_rel*9 + k]  (global layout)

    const int t    = threadIdx.x;
    const int w0   = blockIdx.x * 32;
    const int h0   = blockIdx.y * 8;
    const int zc   = COUT / 64;
    const int n    = blockIdx.z / zc;
    const int co0  = (blockIdx.z % zc) * 64;

    const int a8   = (t >> 5) * 8;        // co sub-base within tile
    const int bl   = t & 31;
    const int r    = bl >> 2;             // pixel row 0..7
    const int wseg = (bl & 3) * 8;        // pixel col seg {0,8,16,24}

    float acc[8][8];
    #pragma unroll
    for (int j = 0; j < 8; ++j)
        #pragma unroll
        for (int p = 0; p < 8; ++p) acc[j][p] = 0.f;

    const float* inb = in + (size_t)n * CIN * HW * HW;
    const float* wtb = wt + (size_t)co0 * (CIN * 9);

    for (int ci0 = 0; ci0 < CIN; ci0 += 8) {
        __syncthreads();
        // stage input tile: 8ci x 10h x 34w (zero-padded borders)
        for (int e = t; e < 2720; e += 256) {
            int ci  = e / 340;
            int rem = e - ci * 340;
            int hh  = rem / 34;
            int ww  = rem - hh * 34;
            int gh  = h0 + hh - 1;
            int gw  = w0 + ww - 1;
            float v = 0.f;
            if ((unsigned)gh < 64u && (unsigned)gw < 64u)
                v = inb[((size_t)(ci0 + ci) * HW + gh) * HW + gw];
            s_in[ci][hh][ww] = v;
        }
        // stage weights: 64co x 72 (ci_rel*9+k), global-contiguous per co
        {
            const float* wb = wtb + (size_t)ci0 * 9;
            for (int e = t; e < 4608; e += 256) {
                int cr  = e / 72;
                int kci = e - cr * 72;
                s_w[cr][kci] = wb[(size_t)cr * (CIN * 9) + kci];
            }
        }
        __syncthreads();

        #pragma unroll
        for (int ci = 0; ci < 8; ++ci) {
            #pragma unroll
            for (int kh = 0; kh < 3; ++kh) {
                const float* row = &s_in[ci][r + kh][wseg];
                float x[10];
                float4 xa = *(const float4*)(row);
                float4 xb = *(const float4*)(row + 4);
                x[0]=xa.x; x[1]=xa.y; x[2]=xa.z; x[3]=xa.w;
                x[4]=xb.x; x[5]=xb.y; x[6]=xb.z; x[7]=xb.w;
                x[8]=row[8]; x[9]=row[9];
                #pragma unroll
                for (int kw = 0; kw < 3; ++kw) {
                    const int kci = ci * 9 + kh * 3 + kw;
                    #pragma unroll
                    for (int j = 0; j < 8; ++j) {
                        float wv = s_w[a8 + j][kci];   // warp-uniform broadcast
                        #pragma unroll
                        for (int p = 0; p < 8; ++p)
                            acc[j][p] = fmaf(wv, x[kw + p], acc[j][p]);
                    }
                }
            }
        }
    }

    float* op = TO_SBUF ? g_sbuf : out_ext;
    #pragma unroll
    for (int j = 0; j < 8; ++j) {
        int co = co0 + a8 + j;
        float sc = bg[co] * rsqrtf(bv[co] + 1e-5f);
        float bi = bb[co] - bm[co] * sc;
        float vv[8];
        #pragma unroll
        for (int p = 0; p < 8; ++p) {
            float vx = fmaf(acc[j][p], sc, bi);
            vv[p] = vx > 0.f ? vx : 0.f;
        }
        float* ob = op + (((size_t)n * COUT + co) * HW + (h0 + r)) * HW + w0 + wseg;
        *(float4*)(ob)     = make_float4(vv[0], vv[1], vv[2], vv[3]);
        *(float4*)(ob + 4) = make_float4(vv[4], vv[5], vv[6], vv[7]);
    }
}

// ---------------------------------------------------------------------------
// y2[n,h,w] = sum_c other[n,c,h,w]^2  (other = clip_emb2 images 0..1)
// ---------------------------------------------------------------------------
__global__ void y2_kernel(const float* __restrict__ ce2)
{
    int nb = blockIdx.x;
    int n = nb >> 6, h = nb & 63, w = threadIdx.x;
    const float* p = ce2 + ((size_t)n * C2 * HW + h) * HW + w;
    float acc = 0.f;
    for (int c = 0; c < C2; ++c) {
        float v = p[(size_t)c * HW * HW];
        acc = fmaf(v, v, acc);
    }
    g_y2[(n * HW + h) * HW + w] = acc;
}

// ---------------------------------------------------------------------------
// Distance weights: per pixel, 25 shifted dot-products over 128 channels,
// dist = x2 + y2_sh - 2*cross, softmax over 1/(dist+1e-5).
// Block = (n, h) row, 64 threads over w.
// ---------------------------------------------------------------------------
__global__ __launch_bounds__(64)
void wgt_kernel(const float* __restrict__ ce2)
{
    __shared__ float s_oth[5][68];
    __shared__ float s_c2[64];

    int nb = blockIdx.x;
    int n = nb >> 6, h = nb & 63, w = threadIdx.x;

    float acc[25];
    #pragma unroll
    for (int o = 0; o < 25; ++o) acc[o] = 0.f;
    float x2 = 0.f;

    const float* oth = ce2 + (size_t)n       * C2 * HW * HW;
    const float* c2  = ce2 + (size_t)(2 + n) * C2 * HW * HW;

    for (int c = 0; c < C2; ++c) {
        __syncthreads();
        for (int e = w; e < 340; e += 64) {
            int dyi = e / 68;
            int ww  = e - dyi * 68;
            int gh  = h + dyi - 2;
            int gw  = ww - 2;
            float v = 0.f;
            if ((unsigned)gh < 64u && (unsigned)gw < 64u)
                v = oth[((size_t)c * HW + gh) * HW + gw];
            s_oth[dyi][ww] = v;
        }
        s_c2[w] = c2[((size_t)c * HW + h) * HW + w];
        __syncthreads();

        float cv = s_c2[w];
        x2 = fmaf(cv, cv, x2);
        #pragma unroll
        for (int o = 0; o < 25; ++o)
            acc[o] = fmaf(cv, s_oth[o / 5][w + (o % 5)], acc[o]);
    }

    float inv[25];
    #pragma unroll
    for (int o = 0; o < 25; ++o) {
        int gh = h + (o / 5) - 2;
        int gw = w + (o % 5) - 2;
        float y2v = 1e20f;
        if ((unsigned)gh < 64u && (unsigned)gw < 64u)
            y2v = g_y2[(n * HW + gh) * HW + gw];
        float dist = x2 + y2v - 2.f * acc[o];
        inv[o] = 1.f / (dist + 1e-5f);
    }
    float m = inv[0];
    #pragma unroll
    for (int o = 1; o < 25; ++o) m = fmaxf(m, inv[o]);
    float s = 0.f;
    #pragma unroll
    for (int o = 0; o < 25; ++o) { inv[o] = expf(inv[o] - m); s += inv[o]; }
    float rs = 1.f / s;
    #pragma unroll
    for (int o = 0; o < 25; ++o)
        g_wgt[((o * NPAIR + n) * HW + h) * HW + w] = inv[o] * rs;
}

// ---------------------------------------------------------------------------
// Warp + average: final_fea[n,c,h,w] = 0.5*(c_img + (1/25)*sum_o w_[o]*oth_sh)
// Block = (n, h) row, 256 threads = 4 channels x 64 w. Output stored NHWC.
// ---------------------------------------------------------------------------
__global__ __launch_bounds__(256)
void warp_kernel()
{
    __shared__ float s_w25[25][64];
    __shared__ float s_oth[4][5][68];

    int nb = blockIdx.x;
    int n = nb >> 6, h = nb & 63;
    int t = threadIdx.x;

    for (int e = t; e < 1600; e += 256) {
        int o = e >> 6, ww = e & 63;
        s_w25[o][ww] = g_wgt[((o * NPAIR + n) * HW + h) * HW + ww];
    }

    const float* oth = g_sbuf + (size_t)n       * C1 * HW * HW;
    const float* cim = g_sbuf + (size_t)(2 + n) * C1 * HW * HW;
    int cc = t >> 6, w = t & 63;

    for (int c0 = 0; c0 < C1; c0 += 4) {
        __syncthreads();
        for (int e = t; e < 1360; e += 256) {
            int ec  = e / 340;
            int rem = e - ec * 340;
            int rr  = rem / 68;
            int ww  = rem - rr * 68;
            int gh  = h + rr - 2;
            int gw  = ww - 2;
            float v = 0.f;
            if ((unsigned)gh < 64u && (unsigned)gw < 64u)
                v = oth[((size_t)(c0 + ec) * HW + gh) * HW + gw];
            s_oth[ec][rr][ww] = v;
        }
        __syncthreads();

        float civ = cim[((size_t)(c0 + cc) * HW + h) * HW + w];
        float a = 0.f;
        #pragma unroll
        for (int o = 0; o < 25; ++o)
            a = fmaf(s_w25[o][w], s_oth[cc][o / 5][w + (o % 5)], a);
        float res = 0.5f * (civ + a * (1.0f / 25.0f));
        g_final[(((size_t)n * HW + h) * HW + w) * C1 + c0 + cc] = res;
    }
}

// ---------------------------------------------------------------------------
// Transpose last_W (124,256) -> (256,124) for coalesced head reads
// ---------------------------------------------------------------------------
__global__ void wt_kernel(const float* __restrict__ lw)
{
    int o = blockIdx.x, c = threadIdx.x;
    g_WT[c * NCLS + o] = lw[o * 256 + c];
}

// ---------------------------------------------------------------------------
// Head: logits[n,o,h,w] = dot(final_fea[n,:,h,w], W[o,:]) + b[o]; log_softmax
// over o. Block = 8 pixels, 128 threads (one class each; 124 active).
// ---------------------------------------------------------------------------
__global__ __launch_bounds__(128)
void head_kernel(const float* __restrict__ lb, float* __restrict__ xout)
{
    __shared__ float s_x[8][256];
    __shared__ float s_red[128];

    int pg = blockIdx.x;
    int t  = threadIdx.x;

    for (int e = t; e < 2048; e += 128) {
        int pp = e >> 8, c = e & 255;
        s_x[pp][c] = g_final[((size_t)pg * 8 + pp) * 256 + c];
    }
    __syncthreads();

    float acc[8];
    #pragma unroll
    for (int pp = 0; pp < 8; ++pp) acc[pp] = 0.f;

    if (t < NCLS) {
        for (int c = 0; c < 256; ++c) {
            float wv = g_WT[c * NCLS + t];
            #pragma unroll
            for (int pp = 0; pp < 8; ++pp)
                acc[pp] = fmaf(s_x[pp][c], wv, acc[pp]);
        }
        float bias = lb[t];
        #pragma unroll
        for (int pp = 0; pp < 8; ++pp) acc[pp] += bias;
    }

    for (int pp = 0; pp < 8; ++pp) {
        __syncthreads();
        s_red[t] = (t < NCLS) ? acc[pp] : -3.4e38f;
        __syncthreads();
        for (int s = 64; s > 0; s >>= 1) {
            if (t < s) s_red[t] = fmaxf(s_red[t], s_red[t + s]);
            __syncthreads();
        }
        float mx = s_red[0];
        __syncthreads();
        s_red[t] = (t < NCLS) ? expf(acc[pp] - mx) : 0.f;
        __syncthreads();
        for (int s = 64; s > 0; s >>= 1) {
            if (t < s) s_red[t] += s_red[t + s];
            __syncthreads();
        }
        float lse = mx + logf(s_red[0]);

        int pix = pg * 8 + pp;
        int n = pix >> 12, h = (pix >> 6) & 63, w = pix & 63;
        if (t < NCLS)
            xout[(((size_t)n * NCLS + t) * HW + h) * HW + w] = acc[pp] - lse;
    }
}

// ---------------------------------------------------------------------------
extern "C" void kernel_launch(void* const* d_in, const int* in_sizes, int n_in,
                              void* d_out, int out_size)
{
    const float* clip  = (const float*)d_in[0];
    // d_in[1] = clip_num (always 2)
    const float* embW  = (const float*)d_in[2];
    const float* eg    = (const float*)d_in[3];
    const float* eb    = (const float*)d_in[4];
    const float* em    = (const float*)d_in[5];
    const float* ev    = (const float*)d_in[6];
    const float* emb2W = (const float*)d_in[7];
    const float* e2g   = (const float*)d_in[8];
    const float* e2b   = (const float*)d_in[9];
    const float* e2m   = (const float*)d_in[10];
    const float* e2v   = (const float*)d_in[11];
    const float* lastW = (const float*)d_in[12];
    const float* lastb = (const float*)d_in[13];

    float* xout = (float*)d_out;
    float* ce2  = (float*)d_out + X_ELEMS;   // clip_emb2 lives in the output

    // conv emb2: 512->128, writes clip_emb2 output region
    conv3x3_bn_relu<C2, false><<<dim3(2, 8, NIMG * (C2 / 64)), 256>>>(
        clip, emb2W, e2g, e2b, e2m, e2v, ce2);
    // conv emb: 512->256, writes g_sbuf
    conv3x3_bn_relu<C1, true><<<dim3(2, 8, NIMG * (C1 / 64)), 256>>>(
        clip, embW, eg, eb, em, ev, nullptr);

    y2_kernel <<<NPAIR * HW, 64>>>(ce2);
    wgt_kernel<<<NPAIR * HW, 64>>>(ce2);
    warp_kernel<<<NPAIR * HW, 256>>>();
    wt_kernel  <<<NCLS, 256>>>(lastW);
    head_kernel<<<(NPAIR * HW * HW) / 8, 128>>>(lastb, xout);
}

// round 2
// speedup vs baseline: 1.1054x; 1.1054x over previous
#include <cuda_runtime.h>
#include <math.h>

// ---------------------------------------------------------------------------
// WarpNet: two 3x3 conv+BN+ReLU (512->128, 512->256), shifted-window softmax
// distance weights (d=2, k=5), weighted warp + average, 1x1 conv head (124
// classes) + log_softmax.
// Round 2: packed f32x2 FMA in the convs (2x fma-pipe throughput on sm_103a),
// wgt_kernel restructured for 4x parallelism (256 thr, channel-split).
// ---------------------------------------------------------------------------

#define NIMG   4
#define CIN    512
#define HW     64
#define C1     256   // emb channels
#define C2     128   // emb2 channels
#define NCLS   124
#define NPAIR  2

#define X_ELEMS (2 * NCLS * HW * HW)

typedef unsigned long long u64;

__device__ __forceinline__ u64 pk2(float lo, float hi) {
    u64 r; asm("mov.b64 %0, {%1, %2};" : "=l"(r) : "f"(lo), "f"(hi)); return r;
}
__device__ __forceinline__ void fma2(u64& d, u64 a, u64 b) {
    asm("fma.rn.f32x2 %0, %1, %2, %0;" : "+l"(d) : "l"(a), "l"(b));
}
__device__ __forceinline__ float2 upk2(u64 v) {
    float2 f; asm("mov.b64 {%0, %1}, %2;" : "=f"(f.x), "=f"(f.y) : "l"(v)); return f;
}

// Scratch (device globals — no allocations allowed)
__device__ float g_sbuf [NIMG * C1 * HW * HW];        // clip_emb_s (NCHW)
__device__ float g_y2   [NPAIR * HW * HW];            // sum_c other^2
__device__ float g_wgt  [25 * NPAIR * HW * HW];       // softmax weights (o,n,h,w)
__device__ float g_final[NPAIR * HW * HW * C1];       // final_fea, NHWC
__device__ float g_WT   [256 * NCLS];                 // last_W transposed (c, o)

// ---------------------------------------------------------------------------
// Conv 3x3 SAME + BN + ReLU.  Block tile: 64 out-channels x (8h x 32w) pixels,
// 256 threads, each thread computes 8co x 8px (as 4 packed f32x2 pairs).
// K loop in chunks of 8 input channels staged in smem.
// ---------------------------------------------------------------------------
template<int COUT, bool TO_SBUF>
__global__ __launch_bounds__(256, 2)
void conv3x3_bn_relu(const float* __restrict__ in,  const float* __restrict__ wt,
                     const float* __restrict__ bg,  const float* __restrict__ bb,
                     const float* __restrict__ bm,  const float* __restrict__ bv,
                     float* __restrict__ out_ext)
{
    __shared__ float s_in[8][10][36];   // [ci][h0-1..h0+8][w0-1..w0+32] (+pad)
    __shared__ float s_w [64][72];      // [co_rel][ci_rel*9 + k]

    const int t    = threadIdx.x;
    const int w0   = blockIdx.x * 32;
    const int h0   = blockIdx.y * 8;
    const int zc   = COUT / 64;
    const int n    = blockIdx.z / zc;
    const int co0  = (blockIdx.z % zc) * 64;

    const int a8   = (t >> 5) * 8;        // co sub-base within tile
    const int bl   = t & 31;
    const int r    = bl >> 2;             // pixel row 0..7
    const int wseg = (bl & 3) * 8;        // pixel col seg {0,8,16,24}

    u64 acc[8][4];                        // [co][pixel-pair]
    #pragma unroll
    for (int j = 0; j < 8; ++j)
        #pragma unroll
        for (int q = 0; q < 4; ++q) acc[j][q] = 0ull;

    const float* inb = in + (size_t)n * CIN * HW * HW;
    const float* wtb = wt + (size_t)co0 * (CIN * 9);

    for (int ci0 = 0; ci0 < CIN; ci0 += 8) {
        __syncthreads();
        // stage input tile: 8ci x 10h x 34w (zero-padded borders)
        for (int e = t; e < 2720; e += 256) {
            int ci  = e / 340;
            int rem = e - ci * 340;
            int hh  = rem / 34;
            int ww  = rem - hh * 34;
            int gh  = h0 + hh - 1;
            int gw  = w0 + ww - 1;
            float v = 0.f;
            if ((unsigned)gh < 64u && (unsigned)gw < 64u)
                v = inb[((size_t)(ci0 + ci) * HW + gh) * HW + gw];
            s_in[ci][hh][ww] = v;
        }
        // stage weights: 64co x 72 (ci_rel*9+k)
        {
            const float* wb = wtb + (size_t)ci0 * 9;
            for (int e = t; e < 4608; e += 256) {
                int cr  = e / 72;
                int kci = e - cr * 72;
                s_w[cr][kci] = wb[(size_t)cr * (CIN * 9) + kci];
            }
        }
        __syncthreads();

        #pragma unroll
        for (int ci = 0; ci < 8; ++ci) {
            #pragma unroll
            for (int kh = 0; kh < 3; ++kh) {
                const float* row = &s_in[ci][r + kh][wseg];
                float x[10];
                float4 xa = *(const float4*)(row);
                float4 xb = *(const float4*)(row + 4);
                x[0]=xa.x; x[1]=xa.y; x[2]=xa.z; x[3]=xa.w;
                x[4]=xb.x; x[5]=xb.y; x[6]=xb.z; x[7]=xb.w;
                x[8]=row[8]; x[9]=row[9];
                u64 pk[9];
                #pragma unroll
                for (int i = 0; i < 9; ++i) pk[i] = pk2(x[i], x[i + 1]);
                #pragma unroll
                for (int kw = 0; kw < 3; ++kw) {
                    const int kci = ci * 9 + kh * 3 + kw;
                    #pragma unroll
                    for (int j = 0; j < 8; ++j) {
                        float wv = s_w[a8 + j][kci];   // warp-uniform broadcast
                        u64 wp = pk2(wv, wv);
                        fma2(acc[j][0], wp, pk[kw]);
                        fma2(acc[j][1], wp, pk[kw + 2]);
                        fma2(acc[j][2], wp, pk[kw + 4]);
                        fma2(acc[j][3], wp, pk[kw + 6]);
                    }
                }
            }
        }
    }

    float* op = TO_SBUF ? g_sbuf : out_ext;
    #pragma unroll
    for (int j = 0; j < 8; ++j) {
        int co = co0 + a8 + j;
        float sc = bg[co] * rsqrtf(bv[co] + 1e-5f);
        float bi = bb[co] - bm[co] * sc;
        float vv[8];
        #pragma unroll
        for (int q = 0; q < 4; ++q) {
            float2 f = upk2(acc[j][q]);
            float v0 = fmaf(f.x, sc, bi);
            float v1 = fmaf(f.y, sc, bi);
            vv[2*q]   = v0 > 0.f ? v0 : 0.f;
            vv[2*q+1] = v1 > 0.f ? v1 : 0.f;
        }
        float* ob = op + (((size_t)n * COUT + co) * HW + (h0 + r)) * HW + w0 + wseg;
        *(float4*)(ob)     = make_float4(vv[0], vv[1], vv[2], vv[3]);
        *(float4*)(ob + 4) = make_float4(vv[4], vv[5], vv[6], vv[7]);
    }
}

// ---------------------------------------------------------------------------
// y2[n,h,w] = sum_c other[n,c,h,w]^2  (other = clip_emb2 images 0..1)
// ---------------------------------------------------------------------------
__global__ void y2_kernel(const float* __restrict__ ce2)
{
    int nb = blockIdx.x;
    int n = nb >> 6, h = nb & 63, w = threadIdx.x;
    const float* p = ce2 + ((size_t)n * C2 * HW + h) * HW + w;
    float acc = 0.f;
    for (int c = 0; c < C2; ++c) {
        float v = p[(size_t)c * HW * HW];
        acc = fmaf(v, v, acc);
    }
    g_y2[(n * HW + h) * HW + w] = acc;
}

// ---------------------------------------------------------------------------
// Distance weights.  Block = (n, h) row, 256 threads = 4 channel-groups x 64 w.
// Each group accumulates 25 shifted dot-product partials over its channels;
// partials reduced through smem, then softmax on the cg==0 quarter.
// ---------------------------------------------------------------------------
__global__ __launch_bounds__(256)
void wgt_kernel(const float* __restrict__ ce2)
{
    __shared__ float s_oth[4][5][68];
    __shared__ float s_acc[26][4][64];

    int nb = blockIdx.x;
    int n = nb >> 6, h = nb & 63;
    int t = threadIdx.x;
    int cg = t >> 6, w = t & 63;

    float acc[25];
    #pragma unroll
    for (int o = 0; o < 25; ++o) acc[o] = 0.f;
    float x2 = 0.f;

    const float* oth = ce2 + (size_t)n       * C2 * HW * HW;
    const float* c2  = ce2 + (size_t)(2 + n) * C2 * HW * HW;

    for (int c0 = 0; c0 < C2; c0 += 4) {
        __syncthreads();
        for (int e = t; e < 1360; e += 256) {
            int ec  = e / 340;
            int rem = e - ec * 340;
            int rr  = rem / 68;
            int ww  = rem - rr * 68;
            int gh  = h + rr - 2;
            int gw  = ww - 2;
            float v = 0.f;
            if ((unsigned)gh < 64u && (unsigned)gw < 64u)
                v = oth[((size_t)(c0 + ec) * HW + gh) * HW + gw];
            s_oth[ec][rr][ww] = v;
        }
        __syncthreads();

        float cv = c2[((size_t)(c0 + cg) * HW + h) * HW + w];
        x2 = fmaf(cv, cv, x2);
        #pragma unroll
        for (int o = 0; o < 25; ++o)
            acc[o] = fmaf(cv, s_oth[cg][o / 5][w + (o % 5)], acc[o]);
    }

    #pragma unroll
    for (int o = 0; o < 25; ++o) s_acc[o][cg][w] = acc[o];
    s_acc[25][cg][w] = x2;
    __syncthreads();

    if (cg == 0) {
        float X2 = s_acc[25][0][w] + s_acc[25][1][w] + s_acc[25][2][w] + s_acc[25][3][w];
        float inv[25];
        #pragma unroll
        for (int o = 0; o < 25; ++o) {
            float cr = s_acc[o][0][w] + s_acc[o][1][w] + s_acc[o][2][w] + s_acc[o][3][w];
            int gh = h + (o / 5) - 2;
            int gw = w + (o % 5) - 2;
            float y2v = 1e20f;
            if ((unsigned)gh < 64u && (unsigned)gw < 64u)
                y2v = g_y2[(n * HW + gh) * HW + gw];
            float dist = X2 + y2v - 2.f * cr;
            inv[o] = 1.f / (dist + 1e-5f);
        }
        float m = inv[0];
        #pragma unroll
        for (int o = 1; o < 25; ++o) m = fmaxf(m, inv[o]);
        float s = 0.f;
        #pragma unroll
        for (int o = 0; o < 25; ++o) { inv[o] = expf(inv[o] - m); s += inv[o]; }
        float rs = 1.f / s;
        #pragma unroll
        for (int o = 0; o < 25; ++o)
            g_wgt[((o * NPAIR + n) * HW + h) * HW + w] = inv[o] * rs;
    }
}

// ---------------------------------------------------------------------------
// Warp + average: final_fea[n,c,h,w] = 0.5*(c_img + (1/25)*sum_o w_[o]*oth_sh)
// Block = (n, h) row, 256 threads = 4 channels x 64 w. Output stored NHWC.
// ---------------------------------------------------------------------------
__global__ __launch_bounds__(256)
void warp_kernel()
{
    __shared__ float s_w25[25][64];
    __shared__ float s_oth[4][5][68];

    int nb = blockIdx.x;
    int n = nb >> 6, h = nb & 63;
    int t = threadIdx.x;

    for (int e = t; e < 1600; e += 256) {
        int o = e >> 6, ww = e & 63;
        s_w25[o][ww] = g_wgt[((o * NPAIR + n) * HW + h) * HW + ww];
    }

    const float* oth = g_sbuf + (size_t)n       * C1 * HW * HW;
    const float* cim = g_sbuf + (size_t)(2 + n) * C1 * HW * HW;
    int cc = t >> 6, w = t & 63;

    for (int c0 = 0; c0 < C1; c0 += 4) {
        __syncthreads();
        for (int e = t; e < 1360; e += 256) {
            int ec  = e / 340;
            int rem = e - ec * 340;
            int rr  = rem / 68;
            int ww  = rem - rr * 68;
            int gh  = h + rr - 2;
            int gw  = ww - 2;
            float v = 0.f;
            if ((unsigned)gh < 64u && (unsigned)gw < 64u)
                v = oth[((size_t)(c0 + ec) * HW + gh) * HW + gw];
            s_oth[ec][rr][ww] = v;
        }
        __syncthreads();

        float civ = cim[((size_t)(c0 + cc) * HW + h) * HW + w];
        float a = 0.f;
        #pragma unroll
        for (int o = 0; o < 25; ++o)
            a = fmaf(s_w25[o][w], s_oth[cc][o / 5][w + (o % 5)], a);
        float res = 0.5f * (civ + a * (1.0f / 25.0f));
        g_final[(((size_t)n * HW + h) * HW + w) * C1 + c0 + cc] = res;
    }
}

// ---------------------------------------------------------------------------
__global__ void wt_kernel(const float* __restrict__ lw)
{
    int o = blockIdx.x, c = threadIdx.x;
    g_WT[c * NCLS + o] = lw[o * 256 + c];
}

// ---------------------------------------------------------------------------
// Head: logits + log_softmax over 124 classes. Block = 8 pixels, 128 threads.
// ---------------------------------------------------------------------------
__global__ __launch_bounds__(128)
void head_kernel(const float* __restrict__ lb, float* __restrict__ xout)
{
    __shared__ float s_x[8][256];
    __shared__ float s_red[128];

    int pg = blockIdx.x;
    int t  = threadIdx.x;

    for (int e = t; e < 2048; e += 128) {
        int pp = e >> 8, c = e & 255;
        s_x[pp][c] = g_final[((size_t)pg * 8 + pp) * 256 + c];
    }
    __syncthreads();

    float acc[8];
    #pragma unroll
    for (int pp = 0; pp < 8; ++pp) acc[pp] = 0.f;

    if (t < NCLS) {
        for (int c = 0; c < 256; ++c) {
            float wv = g_WT[c * NCLS + t];
            #pragma unroll
            for (int pp = 0; pp < 8; ++pp)
                acc[pp] = fmaf(s_x[pp][c], wv, acc[pp]);
        }
        float bias = lb[t];
        #pragma unroll
        for (int pp = 0; pp < 8; ++pp) acc[pp] += bias;
    }

    for (int pp = 0; pp < 8; ++pp) {
        __syncthreads();
        s_red[t] = (t < NCLS) ? acc[pp] : -3.4e38f;
        __syncthreads();
        for (int s = 64; s > 0; s >>= 1) {
            if (t < s) s_red[t] = fmaxf(s_red[t], s_red[t + s]);
            __syncthreads();
        }
        float mx = s_red[0];
        __syncthreads();
        s_red[t] = (t < NCLS) ? expf(acc[pp] - mx) : 0.f;
        __syncthreads();
        for (int s = 64; s > 0; s >>= 1) {
            if (t < s) s_red[t] += s_red[t + s];
            __syncthreads();
        }
        float lse = mx + logf(s_red[0]);

        int pix = pg * 8 + pp;
        int n = pix >> 12, h = (pix >> 6) & 63, w = pix & 63;
        if (t < NCLS)
            xout[(((size_t)n * NCLS + t) * HW + h) * HW + w] = acc[pp] - lse;
    }
}

// ---------------------------------------------------------------------------
extern "C" void kernel_launch(void* const* d_in, const int* in_sizes, int n_in,
                              void* d_out, int out_size)
{
    const float* clip  = (const float*)d_in[0];
    const float* embW  = (const float*)d_in[2];
    const float* eg    = (const float*)d_in[3];
    const float* eb    = (const float*)d_in[4];
    const float* em    = (const float*)d_in[5];
    const float* ev    = (const float*)d_in[6];
    const float* emb2W = (const float*)d_in[7];
    const float* e2g   = (const float*)d_in[8];
    const float* e2b   = (const float*)d_in[9];
    const float* e2m   = (const float*)d_in[10];
    const float* e2v   = (const float*)d_in[11];
    const float* lastW = (const float*)d_in[12];
    const float* lastb = (const float*)d_in[13];

    float* xout = (float*)d_out;
    float* ce2  = (float*)d_out + X_ELEMS;   // clip_emb2 lives in the output

    conv3x3_bn_relu<C2, false><<<dim3(2, 8, NIMG * (C2 / 64)), 256>>>(
        clip, emb2W, e2g, e2b, e2m, e2v, ce2);
    conv3x3_bn_relu<C1, true><<<dim3(2, 8, NIMG * (C1 / 64)), 256>>>(
        clip, embW, eg, eb, em, ev, nullptr);

    y2_kernel <<<NPAIR * HW, 64>>>(ce2);
    wgt_kernel<<<NPAIR * HW, 256>>>(ce2);
    warp_kernel<<<NPAIR * HW, 256>>>();
    wt_kernel  <<<NCLS, 256>>>(lastW);
    head_kernel<<<(NPAIR * HW * HW) / 8, 128>>>(lastb, xout);
}

// round 3
// speedup vs baseline: 1.1090x; 1.0032x over previous
#include <cuda_runtime.h>
#include <math.h>

// ---------------------------------------------------------------------------
// WarpNet: two 3x3 conv+BN+ReLU (512->128, 512->256), shifted-window softmax
// distance weights (d=2, k=5), weighted warp + average, 1x1 conv head (124
// classes) + log_softmax.
// Round 2: packed f32x2 FMA in the convs (2x fma-pipe throughput on sm_103a),
// wgt_kernel restructured for 4x parallelism (256 thr, channel-split).
// ---------------------------------------------------------------------------

#define NIMG   4
#define CIN    512
#define HW     64
#define C1     256   // emb channels
#define C2     128   // emb2 channels
#define NCLS   124
#define NPAIR  2

#define X_ELEMS (2 * NCLS * HW * HW)

typedef unsigned long long u64;

__device__ __forceinline__ u64 pk2(float lo, float hi) {
    u64 r; asm("mov.b64 %0, {%1, %2};" : "=l"(r) : "f"(lo), "f"(hi)); return r;
}
__device__ __forceinline__ void fma2(u64& d, u64 a, u64 b) {
    asm("fma.rn.f32x2 %0, %1, %2, %0;" : "+l"(d) : "l"(a), "l"(b));
}
__device__ __forceinline__ float2 upk2(u64 v) {
    float2 f; asm("mov.b64 {%0, %1}, %2;" : "=f"(f.x), "=f"(f.y) : "l"(v)); return f;
}

// Scratch (device globals — no allocations allowed)
__device__ float g_sbuf [NIMG * C1 * HW * HW];        // clip_emb_s (NCHW)
__device__ float g_y2   [NPAIR * HW * HW];            // sum_c other^2
__device__ float g_wgt  [25 * NPAIR * HW * HW];       // softmax weights (o,n,h,w)
__device__ float g_final[NPAIR * HW * HW * C1];       // final_fea, NHWC
__device__ float g_WT   [256 * NCLS];                 // last_W transposed (c, o)

// ---------------------------------------------------------------------------
// Conv 3x3 SAME + BN + ReLU.  Block tile: 64 out-channels x (8h x 32w) pixels,
// 256 threads, each thread computes 8co x 8px (as 4 packed f32x2 pairs).
// K loop in chunks of 8 input channels staged in smem.
// ---------------------------------------------------------------------------
template<int COUT, bool TO_SBUF>
__global__ __launch_bounds__(256, 2)
void conv3x3_bn_relu(const float* __restrict__ in,  const float* __restrict__ wt,
                     const float* __restrict__ bg,  const float* __restrict__ bb,
                     const float* __restrict__ bm,  const float* __restrict__ bv,
                     float* __restrict__ out_ext)
{
    __shared__ float s_in[8][10][36];   // [ci][h0-1..h0+8][w0-1..w0+32] (+pad)
    __shared__ float s_w [64][72];      // [co_rel][ci_rel*9 + k]

    const int t    = threadIdx.x;
    const int w0   = blockIdx.x * 32;
    const int h0   = blockIdx.y * 8;
    const int zc   = COUT / 64;
    const int n    = blockIdx.z / zc;
    const int co0  = (blockIdx.z % zc) * 64;

    const int a8   = (t >> 5) * 8;        // co sub-base within tile
    const int bl   = t & 31;
    const int r    = bl >> 2;             // pixel row 0..7
    const int wseg = (bl & 3) * 8;        // pixel col seg {0,8,16,24}

    u64 acc[8][4];                        // [co][pixel-pair]
    #pragma unroll
    for (int j = 0; j < 8; ++j)
        #pragma unroll
        for (int q = 0; q < 4; ++q) acc[j][q] = 0ull;

    const float* inb = in + (size_t)n * CIN * HW * HW;
    const float* wtb = wt + (size_t)co0 * (CIN * 9);

    for (int ci0 = 0; ci0 < CIN; ci0 += 8) {
        __syncthreads();
        // stage input tile: 8ci x 10h x 34w (zero-padded borders)
        for (int e = t; e < 2720; e += 256) {
            int ci  = e / 340;
            int rem = e - ci * 340;
            int hh  = rem / 34;
            int ww  = rem - hh * 34;
            int gh  = h0 + hh - 1;
            int gw  = w0 + ww - 1;
            float v = 0.f;
            if ((unsigned)gh < 64u && (unsigned)gw < 64u)
                v = inb[((size_t)(ci0 + ci) * HW + gh) * HW + gw];
            s_in[ci][hh][ww] = v;
        }
        // stage weights: 64co x 72 (ci_rel*9+k)
        {
            const float* wb = wtb + (size_t)ci0 * 9;
            for (int e = t; e < 4608; e += 256) {
                int cr  = e / 72;
                int kci = e - cr * 72;
                s_w[cr][kci] = wb[(size_t)cr * (CIN * 9) + kci];
            }
        }
        __syncthreads();

        #pragma unroll
        for (int ci = 0; ci < 8; ++ci) {
            #pragma unroll
            for (int kh = 0; kh < 3; ++kh) {
                const float* row = &s_in[ci][r + kh][wseg];
                float x[10];
                float4 xa = *(const float4*)(row);
                float4 xb = *(const float4*)(row + 4);
                x[0]=xa.x; x[1]=xa.y; x[2]=xa.z; x[3]=xa.w;
                x[4]=xb.x; x[5]=xb.y; x[6]=xb.z; x[7]=xb.w;
                x[8]=row[8]; x[9]=row[9];
                u64 pk[9];
                #pragma unroll
                for (int i = 0; i < 9; ++i) pk[i] = pk2(x[i], x[i + 1]);
                #pragma unroll
                for (int kw = 0; kw < 3; ++kw) {
                    const int kci = ci * 9 + kh * 3 + kw;
                    #pragma unroll
                    for (int j = 0; j < 8; ++j) {
                        float wv = s_w[a8 + j][kci];   // warp-uniform broadcast
                        u64 wp = pk2(wv, wv);
                        fma2(acc[j][0], wp, pk[kw]);
                        fma2(acc[j][1], wp, pk[kw + 2]);
                        fma2(acc[j][2], wp, pk[kw + 4]);
                        fma2(acc[j][3], wp, pk[kw + 6]);
                    }
                }
            }
        }
    }

    float* op = TO_SBUF ? g_sbuf : out_ext;
    #pragma unroll
    for (int j = 0; j < 8; ++j) {
        int co = co0 + a8 + j;
        float sc = bg[co] * rsqrtf(bv[co] + 1e-5f);
        float bi = bb[co] - bm[co] * sc;
        float vv[8];
        #pragma unroll
        for (int q = 0; q < 4; ++q) {
            float2 f = upk2(acc[j][q]);
            float v0 = fmaf(f.x, sc, bi);
            float v1 = fmaf(f.y, sc, bi);
            vv[2*q]   = v0 > 0.f ? v0 : 0.f;
            vv[2*q+1] = v1 > 0.f ? v1 : 0.f;
        }
        float* ob = op + (((size_t)n * COUT + co) * HW + (h0 + r)) * HW + w0 + wseg;
        *(float4*)(ob)     = make_float4(vv[0], vv[1], vv[2], vv[3]);
        *(float4*)(ob + 4) = make_float4(vv[4], vv[5], vv[6], vv[7]);
    }
}

// ---------------------------------------------------------------------------
// y2[n,h,w] = sum_c other[n,c,h,w]^2  (other = clip_emb2 images 0..1)
// ---------------------------------------------------------------------------
__global__ void y2_kernel(const float* __restrict__ ce2)
{
    int nb = blockIdx.x;
    int n = nb >> 6, h = nb & 63, w = threadIdx.x;
    const float* p = ce2 + ((size_t)n * C2 * HW + h) * HW + w;
    float acc = 0.f;
    for (int c = 0; c < C2; ++c) {
        float v = p[(size_t)c * HW * HW];
        acc = fmaf(v, v, acc);
    }
    g_y2[(n * HW + h) * HW + w] = acc;
}

// ---------------------------------------------------------------------------
// Distance weights.  Block = (n, h) row, 256 threads = 4 channel-groups x 64 w.
// Each group accumulates 25 shifted dot-product partials over its channels;
// partials reduced through smem, then softmax on the cg==0 quarter.
// ---------------------------------------------------------------------------
__global__ __launch_bounds__(256)
void wgt_kernel(const float* __restrict__ ce2)
{
    __shared__ float s_oth[4][5][68];
    __shared__ float s_acc[26][4][64];

    int nb = blockIdx.x;
    int n = nb >> 6, h = nb & 63;
    int t = threadIdx.x;
    int cg = t >> 6, w = t & 63;

    float acc[25];
    #pragma unroll
    for (int o = 0; o < 25; ++o) acc[o] = 0.f;
    float x2 = 0.f;

    const float* oth = ce2 + (size_t)n       * C2 * HW * HW;
    const float* c2  = ce2 + (size_t)(2 + n) * C2 * HW * HW;

    for (int c0 = 0; c0 < C2; c0 += 4) {
        __syncthreads();
        for (int e = t; e < 1360; e += 256) {
            int ec  = e / 340;
            int rem = e - ec * 340;
            int rr  = rem / 68;
            int ww  = rem - rr * 68;
            int gh  = h + rr - 2;
            int gw  = ww - 2;
            float v = 0.f;
            if ((unsigned)gh < 64u && (unsigned)gw < 64u)
                v = oth[((size_t)(c0 + ec) * HW + gh) * HW + gw];
            s_oth[ec][rr][ww] = v;
        }
        __syncthreads();

        float cv = c2[((size_t)(c0 + cg) * HW + h) * HW + w];
        x2 = fmaf(cv, cv, x2);
        #pragma unroll
        for (int o = 0; o < 25; ++o)
            acc[o] = fmaf(cv, s_oth[cg][o / 5][w + (o % 5)], acc[o]);
    }

    #pragma unroll
    for (int o = 0; o < 25; ++o) s_acc[o][cg][w] = acc[o];
    s_acc[25][cg][w] = x2;
    __syncthreads();

    if (cg == 0) {
        float X2 = s_acc[25][0][w] + s_acc[25][1][w] + s_acc[25][2][w] + s_acc[25][3][w];
        float inv[25];
        #pragma unroll
        for (int o = 0; o < 25; ++o) {
            float cr = s_acc[o][0][w] + s_acc[o][1][w] + s_acc[o][2][w] + s_acc[o][3][w];
            int gh = h + (o / 5) - 2;
            int gw = w + (o % 5) - 2;
            float y2v = 1e20f;
            if ((unsigned)gh < 64u && (unsigned)gw < 64u)
                y2v = g_y2[(n * HW + gh) * HW + gw];
            float dist = X2 + y2v - 2.f * cr;
            inv[o] = 1.f / (dist + 1e-5f);
        }
        float m = inv[0];
        #pragma unroll
        for (int o = 1; o < 25; ++o) m = fmaxf(m, inv[o]);
        float s = 0.f;
        #pragma unroll
        for (int o = 0; o < 25; ++o) { inv[o] = expf(inv[o] - m); s += inv[o]; }
        float rs = 1.f / s;
        #pragma unroll
        for (int o = 0; o < 25; ++o)
            g_wgt[((o * NPAIR + n) * HW + h) * HW + w] = inv[o] * rs;
    }
}

// ---------------------------------------------------------------------------
// Warp + average: final_fea[n,c,h,w] = 0.5*(c_img + (1/25)*sum_o w_[o]*oth_sh)
// Block = (n, h) row, 256 threads = 4 channels x 64 w. Output stored NHWC.
// ---------------------------------------------------------------------------
__global__ __launch_bounds__(256)
void warp_kernel()
{
    __shared__ float s_w25[25][64];
    __shared__ float s_oth[4][5][68];

    int nb = blockIdx.x;
    int n = nb >> 6, h = nb & 63;
    int t = threadIdx.x;

    for (int e = t; e < 1600; e += 256) {
        int o = e >> 6, ww = e & 63;
        s_w25[o][ww] = g_wgt[((o * NPAIR + n) * HW + h) * HW + ww];
    }

    const float* oth = g_sbuf + (size_t)n       * C1 * HW * HW;
    const float* cim = g_sbuf + (size_t)(2 + n) * C1 * HW * HW;
    int cc = t >> 6, w = t & 63;

    for (int c0 = 0; c0 < C1; c0 += 4) {
        __syncthreads();
        for (int e = t; e < 1360; e += 256) {
            int ec  = e / 340;
            int rem = e - ec * 340;
            int rr  = rem / 68;
            int ww  = rem - rr * 68;
            int gh  = h + rr - 2;
            int gw  = ww - 2;
            float v = 0.f;
            if ((unsigned)gh < 64u && (unsigned)gw < 64u)
                v = oth[((size_t)(c0 + ec) * HW + gh) * HW + gw];
            s_oth[ec][rr][ww] = v;
        }
        __syncthreads();

        float civ = cim[((size_t)(c0 + cc) * HW + h) * HW + w];
        float a = 0.f;
        #pragma unroll
        for (int o = 0; o < 25; ++o)
            a = fmaf(s_w25[o][w], s_oth[cc][o / 5][w + (o % 5)], a);
        float res = 0.5f * (civ + a * (1.0f / 25.0f));
        g_final[(((size_t)n * HW + h) * HW + w) * C1 + c0 + cc] = res;
    }
}

// ---------------------------------------------------------------------------
__global__ void wt_kernel(const float* __restrict__ lw)
{
    int o = blockIdx.x, c = threadIdx.x;
    g_WT[c * NCLS + o] = lw[o * 256 + c];
}

// ---------------------------------------------------------------------------
// Head: logits + log_softmax over 124 classes. Block = 8 pixels, 128 threads.
// ---------------------------------------------------------------------------
__global__ __launch_bounds__(128)
void head_kernel(const float* __restrict__ lb, float* __restrict__ xout)
{
    __shared__ float s_x[8][256];
    __shared__ float s_red[128];

    int pg = blockIdx.x;
    int t  = threadIdx.x;

    for (int e = t; e < 2048; e += 128) {
        int pp = e >> 8, c = e & 255;
        s_x[pp][c] = g_final[((size_t)pg * 8 + pp) * 256 + c];
    }
    __syncthreads();

    float acc[8];
    #pragma unroll
    for (int pp = 0; pp < 8; ++pp) acc[pp] = 0.f;

    if (t < NCLS) {
        for (int c = 0; c < 256; ++c) {
            float wv = g_WT[c * NCLS + t];
            #pragma unroll
            for (int pp = 0; pp < 8; ++pp)
                acc[pp] = fmaf(s_x[pp][c], wv, acc[pp]);
        }
        float bias = lb[t];
        #pragma unroll
        for (int pp = 0; pp < 8; ++pp) acc[pp] += bias;
    }

    for (int pp = 0; pp < 8; ++pp) {
        __syncthreads();
        s_red[t] = (t < NCLS) ? acc[pp] : -3.4e38f;
        __syncthreads();
        for (int s = 64; s > 0; s >>= 1) {
            if (t < s) s_red[t] = fmaxf(s_red[t], s_red[t + s]);
            __syncthreads();
        }
        float mx = s_red[0];
        __syncthreads();
        s_red[t] = (t < NCLS) ? expf(acc[pp] - mx) : 0.f;
        __syncthreads();
        for (int s = 64; s > 0; s >>= 1) {
            if (t < s) s_red[t] += s_red[t + s];
            __syncthreads();
        }
        float lse = mx + logf(s_red[0]);

        int pix = pg * 8 + pp;
        int n = pix >> 12, h = (pix >> 6) & 63, w = pix & 63;
        if (t < NCLS)
            xout[(((size_t)n * NCLS + t) * HW + h) * HW + w] = acc[pp] - lse;
    }
}

// ---------------------------------------------------------------------------
extern "C" void kernel_launch(void* const* d_in, const int* in_sizes, int n_in,
                              void* d_out, int out_size)
{
    const float* clip  = (const float*)d_in[0];
    const float* embW  = (const float*)d_in[2];
    const float* eg    = (const float*)d_in[3];
    const float* eb    = (const float*)d_in[4];
    const float* em    = (const float*)d_in[5];
    const float* ev    = (const float*)d_in[6];
    const float* emb2W = (const float*)d_in[7];
    const float* e2g   = (const float*)d_in[8];
    const float* e2b   = (const float*)d_in[9];
    const float* e2m   = (const float*)d_in[10];
    const float* e2v   = (const float*)d_in[11];
    const float* lastW = (const float*)d_in[12];
    const float* lastb = (const float*)d_in[13];

    float* xout = (float*)d_out;
    float* ce2  = (float*)d_out + X_ELEMS;   // clip_emb2 lives in the output

    conv3x3_bn_relu<C2, false><<<dim3(2, 8, NIMG * (C2 / 64)), 256>>>(
        clip, emb2W, e2g, e2b, e2m, e2v, ce2);
    conv3x3_bn_relu<C1, true><<<dim3(2, 8, NIMG * (C1 / 64)), 256>>>(
        clip, embW, eg, eb, em, ev, nullptr);

    y2_kernel <<<NPAIR * HW, 64>>>(ce2);
    wgt_kernel<<<NPAIR * HW, 256>>>(ce2);
    warp_kernel<<<NPAIR * HW, 256>>>();
    wt_kernel  <<<NCLS, 256>>>(lastW);
    head_kernel<<<(NPAIR * HW * HW) / 8, 128>>>(lastb, xout);
}